// round 13
// baseline (speedup 1.0000x reference)
#include <cuda_runtime.h>
#include <cuda_fp16.h>
#include <cstdint>

// COO SpMM: out[src[e], :] += att[e] * X[dst[e], :], D = 128 fp32.
//
// R6/R10 champion pipeline + ONE verified improvement: 4B packed edge meta
// (dst<<15 | att*32767) — measured: scatter 51.4 -> 46.6us, spmm unchanged
// (73.664us). Scan is the original proven 3-kernel trio (R12's fused scan23
// cost ~+11us and is reverted).
//
//   1. prep_hist: X fp32->fp16 convert + src histogram (zero-invariant
//      counters: spmm resets them; statics start zero)
//   2-4. scan1 / scan2 / scan3 -> rowptr + cursor
//   5. scatter: packed 4B meta, sorted by src
//   6. spmm: warp-per-node gather-FMA fp16->fp32, streaming store
//
// PACKED CSR only (R3+R8: padded layouts ~4x slower).
// Footprint: X_half 25.6MB + meta 12.8MB + ptrs ~1.2MB = ~40MB << 126MB L2.

#define SCAN_BLK 1024
#define N_MAX 131072
#define E_MAX 3276800

__device__ int      g_count[N_MAX];     // histogram; zero before & after each call
__device__ int      g_cursor[N_MAX];    // scatter fill cursor
__device__ int      g_rowptr[N_MAX + 1];
__device__ int      g_blocksums[N_MAX / SCAN_BLK];
__device__ unsigned g_edge[E_MAX];                  // dst<<15 | att15
__device__ uint2    g_xh[(size_t)N_MAX * 32];       // X fp16: 32 uint2/row

__device__ __forceinline__ bool detect64(const void* edges) {
    const int* w = (const int*)edges;
    return (w[1] == 0 && w[3] == 0 && w[5] == 0);   // ids << 2^31
}

__device__ __forceinline__ unsigned h2_bits(__half2 h) {
    return *reinterpret_cast<unsigned*>(&h);
}

// Fused: convert X -> fp16 (DRAM-stream bound) + histogram src (atomic bound).
__global__ void prep_hist_kernel(const float4* __restrict__ X, int N,
                                 const void* __restrict__ edges, int E) {
    int stride = gridDim.x * blockDim.x;
    int tid = blockIdx.x * blockDim.x + threadIdx.x;

    int n4 = N * 32;
    for (int i = tid; i < n4; i += stride) {
        float4 v = __ldcs(X + i);
        g_xh[i] = make_uint2(h2_bits(__floats2half2_rn(v.x, v.y)),
                             h2_bits(__floats2half2_rn(v.z, v.w)));
    }

    const bool is64 = detect64(edges);
    if (is64) {
        const long long* s = (const long long*)edges;
        for (int e = tid; e < E; e += stride)
            atomicAdd(&g_count[(int)s[e]], 1);
    } else {
        const int* s = (const int*)edges;
        for (int e = tid; e < E; e += stride)
            atomicAdd(&g_count[s[e]], 1);
    }
}

__global__ void scan1_kernel() {
    __shared__ int sh[SCAN_BLK];
    int i = blockIdx.x * SCAN_BLK + threadIdx.x;
    int v = g_count[i];
    sh[threadIdx.x] = v;
    __syncthreads();
    #pragma unroll
    for (int off = 1; off < SCAN_BLK; off <<= 1) {
        int t = (threadIdx.x >= off) ? sh[threadIdx.x - off] : 0;
        __syncthreads();
        sh[threadIdx.x] += t;
        __syncthreads();
    }
    g_rowptr[i] = sh[threadIdx.x] - v;
    if (threadIdx.x == SCAN_BLK - 1) g_blocksums[blockIdx.x] = sh[threadIdx.x];
}

__global__ void scan2_kernel(int nblocks) {
    __shared__ int sh[128];
    int v = (threadIdx.x < nblocks) ? g_blocksums[threadIdx.x] : 0;
    sh[threadIdx.x] = v;
    __syncthreads();
    #pragma unroll
    for (int off = 1; off < 128; off <<= 1) {
        int t = (threadIdx.x >= off) ? sh[threadIdx.x - off] : 0;
        __syncthreads();
        sh[threadIdx.x] += t;
        __syncthreads();
    }
    if (threadIdx.x < nblocks) g_blocksums[threadIdx.x] = sh[threadIdx.x] - v;
}

__global__ void scan3_kernel(int npad) {
    int i = blockIdx.x * blockDim.x + threadIdx.x;
    if (i < npad) {
        int r = g_rowptr[i] + g_blocksums[i / SCAN_BLK];
        g_rowptr[i] = r;
        g_cursor[i] = r;
    }
}

// Packed scatter: meta = dst << 15 | round(att * 32767). att in [0,1) so the
// 15-bit quantization adds ~3e-5 relative error (negligible vs fp16 gather).
__global__ void scatter_kernel(const void* __restrict__ edges,
                               const float* __restrict__ att, int E) {
    const bool is64 = detect64(edges);
    int half = E >> 1;
    int stride = gridDim.x * blockDim.x;
    for (int i = blockIdx.x * blockDim.x + threadIdx.x; i < half; i += stride) {
        int s0, s1, d0, d1;
        if (is64) {
            longlong2 s = __ldcs((const longlong2*)edges + i);
            longlong2 d = __ldcs((const longlong2*)((const long long*)edges + E) + i);
            s0 = (int)s.x; s1 = (int)s.y; d0 = (int)d.x; d1 = (int)d.y;
        } else {
            int2 s = __ldcs((const int2*)edges + i);
            int2 d = __ldcs((const int2*)((const int*)edges + E) + i);
            s0 = s.x; s1 = s.y; d0 = d.x; d1 = d.y;
        }
        float2 a = __ldcs((const float2*)att + i);
        unsigned q0 = min(__float2int_rn(a.x * 32767.f), 32767);
        unsigned q1 = min(__float2int_rn(a.y * 32767.f), 32767);
        int p0 = atomicAdd(&g_cursor[s0], 1);
        g_edge[p0] = ((unsigned)d0 << 15) | q0;
        int p1 = atomicAdd(&g_cursor[s1], 1);
        g_edge[p1] = ((unsigned)d1 << 15) | q1;
    }
    if (blockIdx.x == 0 && threadIdx.x == 0 && (E & 1)) {
        int e = E - 1;
        int s, d;
        if (is64) {
            s = (int)((const long long*)edges)[e];
            d = (int)((const long long*)edges)[(long long)E + e];
        } else {
            s = ((const int*)edges)[e];
            d = ((const int*)edges)[(long long)E + e];
        }
        unsigned q = min(__float2int_rn(att[e] * 32767.f), 32767);
        int p = atomicAdd(&g_cursor[s], 1);
        g_edge[p] = ((unsigned)d << 15) | q;
    }
}

__device__ __forceinline__ void meta_fma(unsigned u, uint2 h, float4& acc) {
    float a = (float)(int)(u & 0x7FFFu) * (1.f / 32767.f);
    float2 lo = __half22float2(*(__half2*)&h.x);
    float2 hi = __half22float2(*(__half2*)&h.y);
    acc.x = fmaf(a, lo.x, acc.x); acc.y = fmaf(a, lo.y, acc.y);
    acc.z = fmaf(a, hi.x, acc.z); acc.w = fmaf(a, hi.y, acc.w);
}

// Warp per node (R7 spmm, measured 73.664us): lane l owns feature quad l.
// fp16 gather (8B/lane = 256B/row coalesced), fp32 accumulate, streaming
// store, 8 independent gathers in flight. Resets g_count (zero-invariant).
__global__ void __launch_bounds__(256) spmm_kernel(float4* __restrict__ out, int N) {
    int lane = threadIdx.x & 31;
    int node = (blockIdx.x * blockDim.x + threadIdx.x) >> 5;
    if (node >= N) return;

    int e = __ldg(&g_rowptr[node]);
    int end = __ldg(&g_rowptr[node + 1]);
    if (lane == 0) g_count[node] = 0;       // restore zero-invariant

    float4 acc = make_float4(0.f, 0.f, 0.f, 0.f);

    for (; e + 8 <= end; e += 8) {
        unsigned m[8]; uint2 h[8];
        #pragma unroll
        for (int k = 0; k < 8; k++) m[k] = __ldcs(&g_edge[e + k]);
        #pragma unroll
        for (int k = 0; k < 8; k++) h[k] = __ldg(&g_xh[(size_t)(m[k] >> 15) * 32 + lane]);
        #pragma unroll
        for (int k = 0; k < 8; k++) meta_fma(m[k], h[k], acc);
    }
    for (; e + 2 <= end; e += 2) {
        unsigned m0 = __ldcs(&g_edge[e]);
        unsigned m1 = __ldcs(&g_edge[e + 1]);
        uint2 h0 = __ldg(&g_xh[(size_t)(m0 >> 15) * 32 + lane]);
        uint2 h1 = __ldg(&g_xh[(size_t)(m1 >> 15) * 32 + lane]);
        meta_fma(m0, h0, acc);
        meta_fma(m1, h1, acc);
    }
    if (e < end) {
        unsigned m = __ldcs(&g_edge[e]);
        uint2 h = __ldg(&g_xh[(size_t)(m >> 15) * 32 + lane]);
        meta_fma(m, h, acc);
    }

    __stcs(out + (size_t)node * 32 + lane, acc);
}

extern "C" void kernel_launch(void* const* d_in, const int* in_sizes, int n_in,
                              void* d_out, int out_size) {
    const void* edges = d_in[0];               // (2, E) int32 or int64
    const float* att = (const float*)d_in[1];  // (E,)
    const float4* X = (const float4*)d_in[3];  // (N, 128) fp32
    float4* out = (float4*)d_out;

    int E = in_sizes[1];
    int N = out_size / 128;
    int npad = ((N + 1 + SCAN_BLK - 1) / SCAN_BLK) * SCAN_BLK;
    int nsb = npad / SCAN_BLK;                 // <= 128

    prep_hist_kernel<<<2048, 256>>>(X, N, edges, E);
    scan1_kernel<<<nsb, SCAN_BLK>>>();
    scan2_kernel<<<1, 128>>>(nsb);
    scan3_kernel<<<(npad + 255) / 256, 256>>>(npad);
    scatter_kernel<<<2048, 256>>>(edges, att, E);
    spmm_kernel<<<(N + 7) / 8, 256>>>(out, N);
}

// round 14
// speedup vs baseline: 1.1163x; 1.1163x over previous
#include <cuda_runtime.h>
#include <cuda_fp16.h>
#include <cstdint>

// COO SpMM: out[src[e], :] += att[e] * X[dst[e], :], D = 128 fp32.
//
// R6/R10 champion (141.4us) with ONE spmm change: edge meta stores the row
// BYTE OFFSET (dst << 8) instead of the node id, so the issue-bound spmm
// inner loop does 1 IADD per gather address instead of 2 IMAD.WIDE.
// The shift runs in scatter, whose ALU pipe is idle (4.5% issue, measured).
//
//   1. prep_hist: X fp32->fp16 convert + src histogram (zero-invariant
//      counters: spmm resets them; statics start zero)
//   2-4. scan1 / scan2 / scan3 -> rowptr + cursor
//   5. scatter packed (dst<<8, att_f32), sorted by src
//   6. spmm: warp-per-node gather-FMA fp16->fp32, streaming store
//
// PACKED CSR only (R3+R8: padded layouts ~4x slower).
// Footprint: X_half 25.6MB + meta 25.6MB + ptrs ~1.2MB = ~53MB << 126MB L2.

#define SCAN_BLK 1024
#define N_MAX 131072
#define E_MAX 3276800

__device__ int    g_count[N_MAX];     // histogram; zero before & after each call
__device__ int    g_cursor[N_MAX];    // scatter fill cursor
__device__ int    g_rowptr[N_MAX + 1];
__device__ int    g_blocksums[N_MAX / SCAN_BLK];
__device__ int2   g_edge[E_MAX];                    // (dst*256, att bits)
__device__ uint2  g_xh[(size_t)N_MAX * 32];         // X fp16: 256B per row

__device__ __forceinline__ bool detect64(const void* edges) {
    const int* w = (const int*)edges;
    return (w[1] == 0 && w[3] == 0 && w[5] == 0);   // ids << 2^31
}

__device__ __forceinline__ unsigned h2_bits(__half2 h) {
    return *reinterpret_cast<unsigned*>(&h);
}

// Fused: convert X -> fp16 (DRAM-stream bound) + histogram src (atomic bound).
__global__ void prep_hist_kernel(const float4* __restrict__ X, int N,
                                 const void* __restrict__ edges, int E) {
    int stride = gridDim.x * blockDim.x;
    int tid = blockIdx.x * blockDim.x + threadIdx.x;

    int n4 = N * 32;
    for (int i = tid; i < n4; i += stride) {
        float4 v = __ldcs(X + i);
        g_xh[i] = make_uint2(h2_bits(__floats2half2_rn(v.x, v.y)),
                             h2_bits(__floats2half2_rn(v.z, v.w)));
    }

    const bool is64 = detect64(edges);
    if (is64) {
        const long long* s = (const long long*)edges;
        for (int e = tid; e < E; e += stride)
            atomicAdd(&g_count[(int)s[e]], 1);
    } else {
        const int* s = (const int*)edges;
        for (int e = tid; e < E; e += stride)
            atomicAdd(&g_count[s[e]], 1);
    }
}

__global__ void scan1_kernel() {
    __shared__ int sh[SCAN_BLK];
    int i = blockIdx.x * SCAN_BLK + threadIdx.x;
    int v = g_count[i];
    sh[threadIdx.x] = v;
    __syncthreads();
    #pragma unroll
    for (int off = 1; off < SCAN_BLK; off <<= 1) {
        int t = (threadIdx.x >= off) ? sh[threadIdx.x - off] : 0;
        __syncthreads();
        sh[threadIdx.x] += t;
        __syncthreads();
    }
    g_rowptr[i] = sh[threadIdx.x] - v;
    if (threadIdx.x == SCAN_BLK - 1) g_blocksums[blockIdx.x] = sh[threadIdx.x];
}

__global__ void scan2_kernel(int nblocks) {
    __shared__ int sh[128];
    int v = (threadIdx.x < nblocks) ? g_blocksums[threadIdx.x] : 0;
    sh[threadIdx.x] = v;
    __syncthreads();
    #pragma unroll
    for (int off = 1; off < 128; off <<= 1) {
        int t = (threadIdx.x >= off) ? sh[threadIdx.x - off] : 0;
        __syncthreads();
        sh[threadIdx.x] += t;
        __syncthreads();
    }
    if (threadIdx.x < nblocks) g_blocksums[threadIdx.x] = sh[threadIdx.x] - v;
}

__global__ void scan3_kernel(int npad) {
    int i = blockIdx.x * blockDim.x + threadIdx.x;
    if (i < npad) {
        int r = g_rowptr[i] + g_blocksums[i / SCAN_BLK];
        g_rowptr[i] = r;
        g_cursor[i] = r;
    }
}

// Scatter packed (dst<<8, att bits): the byte-offset shift runs here, where
// the ALU pipe is idle (measured 4.5% issue), not in the issue-bound spmm.
__global__ void scatter_kernel(const void* __restrict__ edges,
                               const float* __restrict__ att, int E) {
    const bool is64 = detect64(edges);
    int half = E >> 1;
    int stride = gridDim.x * blockDim.x;
    for (int i = blockIdx.x * blockDim.x + threadIdx.x; i < half; i += stride) {
        int s0, s1, d0, d1;
        if (is64) {
            longlong2 s = __ldcs((const longlong2*)edges + i);
            longlong2 d = __ldcs((const longlong2*)((const long long*)edges + E) + i);
            s0 = (int)s.x; s1 = (int)s.y; d0 = (int)d.x; d1 = (int)d.y;
        } else {
            int2 s = __ldcs((const int2*)edges + i);
            int2 d = __ldcs((const int2*)((const int*)edges + E) + i);
            s0 = s.x; s1 = s.y; d0 = d.x; d1 = d.y;
        }
        float2 a = __ldcs((const float2*)att + i);
        int p0 = atomicAdd(&g_cursor[s0], 1);
        g_edge[p0] = make_int2(d0 << 8, __float_as_int(a.x));
        int p1 = atomicAdd(&g_cursor[s1], 1);
        g_edge[p1] = make_int2(d1 << 8, __float_as_int(a.y));
    }
    if (blockIdx.x == 0 && threadIdx.x == 0 && (E & 1)) {
        int e = E - 1;
        int s, d;
        if (is64) {
            s = (int)((const long long*)edges)[e];
            d = (int)((const long long*)edges)[(long long)E + e];
        } else {
            s = ((const int*)edges)[e];
            d = ((const int*)edges)[(long long)E + e];
        }
        int p = atomicAdd(&g_cursor[s], 1);
        g_edge[p] = make_int2(d << 8, __float_as_int(att[e]));
    }
}

__device__ __forceinline__ void edge_fma_m(int2 m, uint2 h, float4& acc) {
    float a = __int_as_float(m.y);
    float2 lo = __half22float2(*(__half2*)&h.x);
    float2 hi = __half22float2(*(__half2*)&h.y);
    acc.x = fmaf(a, lo.x, acc.x); acc.y = fmaf(a, lo.y, acc.y);
    acc.z = fmaf(a, hi.x, acc.z); acc.w = fmaf(a, hi.y, acc.w);
}

// Warp per node: lane l owns feature quad l. Gather address = lane-adjusted
// base + meta.x (one IADD, no IMAD.WIDE pair). fp16 gather (8B/lane = 256B
// coalesced row), fp32 FMA, 8 gathers in flight, streaming store. Resets
// g_count (zero-invariant).
__global__ void __launch_bounds__(256) spmm_kernel(float4* __restrict__ out, int N) {
    int lane = threadIdx.x & 31;
    int node = (blockIdx.x * blockDim.x + threadIdx.x) >> 5;
    if (node >= N) return;

    int e = __ldg(&g_rowptr[node]);
    int end = __ldg(&g_rowptr[node + 1]);
    if (lane == 0) g_count[node] = 0;       // restore zero-invariant

    const char* xb = (const char*)g_xh + (lane << 3);   // lane's 8B within row
    float4 acc = make_float4(0.f, 0.f, 0.f, 0.f);

    for (; e + 8 <= end; e += 8) {
        int2 m[8]; uint2 h[8];
        #pragma unroll
        for (int k = 0; k < 8; k++) m[k] = __ldg(&g_edge[e + k]);
        #pragma unroll
        for (int k = 0; k < 8; k++)
            h[k] = __ldg((const uint2*)(xb + (unsigned)m[k].x));
        #pragma unroll
        for (int k = 0; k < 8; k++) edge_fma_m(m[k], h[k], acc);
    }
    for (; e + 2 <= end; e += 2) {
        int2 m0 = __ldg(&g_edge[e]);
        int2 m1 = __ldg(&g_edge[e + 1]);
        uint2 h0 = __ldg((const uint2*)(xb + (unsigned)m0.x));
        uint2 h1 = __ldg((const uint2*)(xb + (unsigned)m1.x));
        edge_fma_m(m0, h0, acc);
        edge_fma_m(m1, h1, acc);
    }
    if (e < end) {
        int2 m = __ldg(&g_edge[e]);
        uint2 h = __ldg((const uint2*)(xb + (unsigned)m.x));
        edge_fma_m(m, h, acc);
    }

    __stcs(out + (size_t)node * 32 + lane, acc);
}

extern "C" void kernel_launch(void* const* d_in, const int* in_sizes, int n_in,
                              void* d_out, int out_size) {
    const void* edges = d_in[0];               // (2, E) int32 or int64
    const float* att = (const float*)d_in[1];  // (E,)
    const float4* X = (const float4*)d_in[3];  // (N, 128) fp32
    float4* out = (float4*)d_out;

    int E = in_sizes[1];
    int N = out_size / 128;
    int npad = ((N + 1 + SCAN_BLK - 1) / SCAN_BLK) * SCAN_BLK;
    int nsb = npad / SCAN_BLK;

    prep_hist_kernel<<<2048, 256>>>(X, N, edges, E);
    scan1_kernel<<<nsb, SCAN_BLK>>>();
    scan2_kernel<<<1, 128>>>(nsb);
    scan3_kernel<<<(npad + 255) / 256, 256>>>(npad);
    scatter_kernel<<<2048, 256>>>(edges, att, E);
    spmm_kernel<<<(N + 7) / 8, 256>>>(out, N);
}